// round 17
// baseline (speedup 1.0000x reference)
#include <cuda_runtime.h>
#include <cuda_bf16.h>
#include <math.h>
#include <stdint.h>

#define NN 50000
#define EE 800000

// ================= scratch (device globals) =================
__device__ uint32_t g_embp[(size_t)NN * 128];  // [x|h1|h2|h3] packed bf16x2 (2 cols/u32)
__device__ uint32_t g_yb0[(size_t)NN * 64];    // y|r ping
__device__ uint32_t g_yb1[(size_t)NN * 64];    // y|r pong
// packed hi/lo weight images, uint4 frags [bh0,bh1,bl0,bl1] (ushort units):
//  pre1@0 (128x64), pre2@16384 (64x64), L0@24576 (64x128), L1@40960 (128x128), L2@73728 (192x128)
__device__ __align__(16) unsigned short g_Bp[122880];
__device__ int   g_cnt[NN];
__device__ int   g_rowptr[NN];
__device__ int   g_cursor[NN];
__device__ int   g_csr_src[EE];
__device__ float g_invdeg[NN];
__device__ int   g_part[256];
__device__ float g_s[256];

__device__ __forceinline__ uint32_t packbf(float x, float y) {
    return ((uint32_t)__bfloat16_as_ushort(__float2bfloat16(y)) << 16) |
           __bfloat16_as_ushort(__float2bfloat16(x));
}
__device__ __forceinline__ float bflo(uint32_t v) { return __uint_as_float(v << 16); }
__device__ __forceinline__ float bfhi(uint32_t v) { return __uint_as_float(v & 0xFFFF0000u); }

// ================= CSR build =================
__global__ void zero_kernel() {
    int i = blockIdx.x * blockDim.x + threadIdx.x;
    if (i < NN) g_cnt[i] = 0;
    if (i < 256) g_s[i] = 0.f;
}
__global__ void hist2_kernel(const int* __restrict__ ei) {
    int e = (blockIdx.x * blockDim.x + threadIdx.x) * 2;
    if (e < EE) {
        int2 d = *(const int2*)&ei[EE + e];
        atomicAdd(&g_cnt[d.x], 1);
        atomicAdd(&g_cnt[d.y], 1);
    }
}
__global__ void part_kernel() {
    __shared__ int s[256];
    int t = threadIdx.x, b = blockIdx.x;
    int i = b * 256 + t;
    int v = (i < NN) ? g_cnt[i] : 0;
    s[t] = v;
    __syncthreads();
    for (int off = 128; off > 0; off >>= 1) {
        if (t < off) s[t] += s[t + off];
        __syncthreads();
    }
    if (t == 0) g_part[b] = s[0];
}
__global__ void fill2_kernel(int nb) {
    __shared__ int sp[256];
    __shared__ int sl[256];
    int t = threadIdx.x, b = blockIdx.x;
    sp[t] = (t < nb) ? g_part[t] : 0;
    __syncthreads();
    for (int off = 1; off < 256; off <<= 1) {
        int a = (t >= off) ? sp[t - off] : 0;
        __syncthreads();
        sp[t] += a;
        __syncthreads();
    }
    int blockbase = (b == 0) ? 0 : sp[b - 1];
    int i = b * 256 + t;
    int v = (i < NN) ? g_cnt[i] : 0;
    sl[t] = v;
    __syncthreads();
    for (int off = 1; off < 256; off <<= 1) {
        int a = (t >= off) ? sl[t - off] : 0;
        __syncthreads();
        sl[t] += a;
        __syncthreads();
    }
    if (i < NN) {
        int base = blockbase + sl[t] - v;
        g_rowptr[i] = base;
        g_cursor[i] = base;
        g_invdeg[i] = 1.0f / (float)(v > 1 ? v : 1);
    }
}
__global__ void scatter2_kernel(const int* __restrict__ ei) {
    int e = (blockIdx.x * blockDim.x + threadIdx.x) * 2;
    if (e < EE) {
        int2 s = *(const int2*)&ei[e];
        int2 d = *(const int2*)&ei[EE + e];
        int p0 = atomicAdd(&g_cursor[d.x], 1);
        g_csr_src[p0] = s.x;
        int p1 = atomicAdd(&g_cursor[d.y], 1);
        g_csr_src[p1] = s.y;
    }
}

// ================= pack ALL weight images (hi/lo uint4 frags) =================
__device__ __forceinline__ void pack_one(float w, int k, int n, int NTILE, int off_us) {
    int kc = k >> 4, kin = k & 15, nc = n >> 3, nin = n & 7;
    int lane = nin * 4 + ((kin & 7) >> 1);
    int reg = kin >> 3, half = kin & 1;
    int base = ((kc * (NTILE >> 3) + nc) * 32 + lane) * 4;
    __nv_bfloat16 hi = __float2bfloat16(w);
    __nv_bfloat16 lo = __float2bfloat16(w - __bfloat162float(hi));
    g_Bp[off_us + (base + reg) * 2 + half]     = __bfloat16_as_ushort(hi);
    g_Bp[off_us + (base + 2 + reg) * 2 + half] = __bfloat16_as_ushort(lo);
}
__global__ void packAll_kernel(const float* __restrict__ pre_w1, const float* __restrict__ pre_w2,
                               const float* __restrict__ wl0, const float* __restrict__ wr0,
                               const float* __restrict__ wl1, const float* __restrict__ wr1,
                               const float* __restrict__ wl2, const float* __restrict__ wr2,
                               const float* __restrict__ skip) {
    int idx = blockIdx.x * blockDim.x + threadIdx.x;
    if (idx < 8192) {
        int k = idx >> 6, n = idx & 63;
        pack_one(pre_w1[k * 64 + n], k, n, 64, 0);
    } else if (idx < 12288) {
        int j = idx - 8192;
        int k = j >> 6, n = j & 63;
        pack_one(pre_w2[k * 64 + n], k, n, 64, 16384);
    } else if (idx < 20480) {
        int j = idx - 12288;
        int k = j >> 7, n = j & 127;
        float g = 1.f / (1.f + expf(-skip[0]));
        float w = ((n < 64) ? wl0[k * 64 + n] : wr0[k * 64 + (n - 64)]) * g;
        pack_one(w, k, n, 128, 24576);
    } else if (idx < 36864) {
        int j = idx - 20480;
        int k = j >> 7, n = j & 127;
        float g = 1.f / (1.f + expf(-skip[3 + (k >> 6)]));
        float w = ((n < 64) ? wl1[k * 64 + n] : wr1[k * 64 + (n - 64)]) * g;
        pack_one(w, k, n, 128, 40960);
    } else if (idx < 61440) {
        int j = idx - 36864;
        int k = j >> 7, n = j & 127;
        float g = 1.f / (1.f + expf(-skip[6 + (k >> 6)]));
        float w = ((n < 64) ? wl2[k * 64 + n] : wr2[k * 64 + (n - 64)]) * g;
        pack_one(w, k, n, 128, 73728);
    }
}

// ================= HMMA helper =================
__device__ __forceinline__ void mma16816(float* acc, const uint32_t* a,
                                         uint32_t b0, uint32_t b1) {
    asm volatile(
        "mma.sync.aligned.m16n8k16.row.col.f32.bf16.bf16.f32 "
        "{%0,%1,%2,%3}, {%4,%5,%6,%7}, {%8,%9}, {%0,%1,%2,%3};"
        : "+f"(acc[0]), "+f"(acc[1]), "+f"(acc[2]), "+f"(acc[3])
        : "r"(a[0]), "r"(a[1]), "r"(a[2]), "r"(a[3]), "r"(b0), "r"(b1));
}

// ================= shared agg body (reads ybIn, writes embp col base outc) =====
__device__ __forceinline__ void agg_node(const uint32_t* __restrict__ ybIn,
                                         int n, int h, const float* __restrict__ bl,
                                         int outc) {
    const int beg = g_rowptr[n], cnt = g_cnt[n];
    float s0 = 0.f, s1 = 0.f, s2 = 0.f, s3 = 0.f;
    float s4 = 0.f, s5 = 0.f, s6 = 0.f, s7 = 0.f;
    for (int k = 0; k < cnt; k++) {
        int src = g_csr_src[beg + k];
        uint4 v = *(const uint4*)&ybIn[(size_t)src * 64 + 4 * h];
        s0 += bflo(v.x); s1 += bfhi(v.x);
        s2 += bflo(v.y); s3 += bfhi(v.y);
        s4 += bflo(v.z); s5 += bfhi(v.z);
        s6 += bflo(v.w); s7 += bfhi(v.w);
    }
    float inv = g_invdeg[n];
    uint4 rv = *(const uint4*)&ybIn[(size_t)n * 64 + 32 + 4 * h];
    float h0 = fmaxf(s0 * inv + bl[8 * h]     + bflo(rv.x), 0.f);
    float h1 = fmaxf(s1 * inv + bl[8 * h + 1] + bfhi(rv.x), 0.f);
    float h2 = fmaxf(s2 * inv + bl[8 * h + 2] + bflo(rv.y), 0.f);
    float h3 = fmaxf(s3 * inv + bl[8 * h + 3] + bfhi(rv.y), 0.f);
    float h4 = fmaxf(s4 * inv + bl[8 * h + 4] + bflo(rv.z), 0.f);
    float h5 = fmaxf(s5 * inv + bl[8 * h + 5] + bfhi(rv.z), 0.f);
    float h6 = fmaxf(s6 * inv + bl[8 * h + 6] + bflo(rv.w), 0.f);
    float h7 = fmaxf(s7 * inv + bl[8 * h + 7] + bfhi(rv.w), 0.f);
    uint4 o;
    o.x = packbf(h0, h1);
    o.y = packbf(h2, h3);
    o.z = packbf(h4, h5);
    o.w = packbf(h6, h7);
    *(uint4*)&g_embp[(size_t)n * 128 + outc + 4 * h] = o;
}

#define SMS 33  // smem row stride in u32 (32 data + 1 pad)

// ================= fused pre-MLP + L0 GEMM (bf16 A, split W) =================
__global__ void __launch_bounds__(256) fused_pre_kernel(
    const float* __restrict__ X,
    const uint4* __restrict__ B1, const float* __restrict__ b1v,
    const uint4* __restrict__ B2, const float* __restrict__ b2v,
    const uint4* __restrict__ B0,
    uint32_t* __restrict__ embp, uint32_t* __restrict__ yb, int M) {
    __shared__ uint32_t t_s[128 * SMS];
    __shared__ uint32_t x_s[128 * SMS];
    const int tid = threadIdx.x;
    const int wid = tid >> 5, lane = tid & 31;
    const int wm = wid >> 1, wn = wid & 1;
    const int q = lane & 3, tq = lane >> 2;
    const int lr0 = wm * 32 + tq;
    const int gb = blockIdx.x * 128;

    // ---------- phase 1: t = relu(X@W1+b1), K=128, N=64 ----------
    {
        float acc[2][4][4];
#pragma unroll
        for (int m = 0; m < 2; m++)
#pragma unroll
            for (int i = 0; i < 4; i++)
#pragma unroll
                for (int j = 0; j < 4; j++) acc[m][i][j] = 0.f;
        for (int kc = 0; kc < 8; kc++) {
            const int c0 = kc * 16 + 2 * q;
            uint32_t a[2][4];
#pragma unroll
            for (int mf = 0; mf < 2; mf++) {
                int ra = gb + lr0 + mf * 16, rc = ra + 8;
                float2 v00 = make_float2(0.f, 0.f), v01 = v00, v10 = v00, v11 = v00;
                if (ra < M) {
                    v00 = *(const float2*)&X[(size_t)ra * 128 + c0];
                    v01 = *(const float2*)&X[(size_t)ra * 128 + c0 + 8];
                }
                if (rc < M) {
                    v10 = *(const float2*)&X[(size_t)rc * 128 + c0];
                    v11 = *(const float2*)&X[(size_t)rc * 128 + c0 + 8];
                }
                a[mf][0] = packbf(v00.x, v00.y);
                a[mf][1] = packbf(v10.x, v10.y);
                a[mf][2] = packbf(v01.x, v01.y);
                a[mf][3] = packbf(v11.x, v11.y);
            }
            const uint4* bp = B1 + (size_t)(kc * 8 + wn * 4) * 32 + lane;
#pragma unroll
            for (int nc = 0; nc < 4; nc++) {
                uint4 b = bp[nc * 32];
                mma16816(acc[0][nc], a[0], b.x, b.y);
                mma16816(acc[0][nc], a[0], b.z, b.w);
                mma16816(acc[1][nc], a[1], b.x, b.y);
                mma16816(acc[1][nc], a[1], b.z, b.w);
            }
        }
#pragma unroll
        for (int nc = 0; nc < 4; nc++) {
            int col = wn * 32 + nc * 8 + 2 * q;
            float bb0 = b1v[col], bb1 = b1v[col + 1];
#pragma unroll
            for (int mf = 0; mf < 2; mf++) {
                int la = lr0 + mf * 16, lc = la + 8;
                t_s[la * SMS + (col >> 1)] =
                    packbf(fmaxf(acc[mf][nc][0] + bb0, 0.f), fmaxf(acc[mf][nc][1] + bb1, 0.f));
                t_s[lc * SMS + (col >> 1)] =
                    packbf(fmaxf(acc[mf][nc][2] + bb0, 0.f), fmaxf(acc[mf][nc][3] + bb1, 0.f));
            }
        }
    }
    __syncthreads();

    // ---------- phase 2: x = t@W2+b2, K=64, N=64 ----------
    {
        float acc[2][4][4];
#pragma unroll
        for (int m = 0; m < 2; m++)
#pragma unroll
            for (int i = 0; i < 4; i++)
#pragma unroll
                for (int j = 0; j < 4; j++) acc[m][i][j] = 0.f;
        for (int kc = 0; kc < 4; kc++) {
            const int ci = kc * 8 + q;
            uint32_t a[2][4];
#pragma unroll
            for (int mf = 0; mf < 2; mf++) {
                int la = lr0 + mf * 16, lc = la + 8;
                a[mf][0] = t_s[la * SMS + ci];
                a[mf][1] = t_s[lc * SMS + ci];
                a[mf][2] = t_s[la * SMS + ci + 4];
                a[mf][3] = t_s[lc * SMS + ci + 4];
            }
            const uint4* bp = B2 + (size_t)(kc * 8 + wn * 4) * 32 + lane;
#pragma unroll
            for (int nc = 0; nc < 4; nc++) {
                uint4 b = bp[nc * 32];
                mma16816(acc[0][nc], a[0], b.x, b.y);
                mma16816(acc[0][nc], a[0], b.z, b.w);
                mma16816(acc[1][nc], a[1], b.x, b.y);
                mma16816(acc[1][nc], a[1], b.z, b.w);
            }
        }
        __syncthreads();
#pragma unroll
        for (int nc = 0; nc < 4; nc++) {
            int col = wn * 32 + nc * 8 + 2 * q;
            float bb0 = b2v[col], bb1 = b2v[col + 1];
#pragma unroll
            for (int mf = 0; mf < 2; mf++) {
                int la = lr0 + mf * 16, lc = la + 8;
                uint32_t p0 = packbf(acc[mf][nc][0] + bb0, acc[mf][nc][1] + bb1);
                uint32_t p1 = packbf(acc[mf][nc][2] + bb0, acc[mf][nc][3] + bb1);
                x_s[la * SMS + (col >> 1)] = p0;
                if (gb + la < M) embp[(size_t)(gb + la) * 128 + (col >> 1)] = p0;
                x_s[lc * SMS + (col >> 1)] = p1;
                if (gb + lc < M) embp[(size_t)(gb + lc) * 128 + (col >> 1)] = p1;
            }
        }
    }
    __syncthreads();

    // ---------- phase 3: y0|r0 = x@W0g, K=64, N=128 ----------
    {
        float acc[2][8][4];
#pragma unroll
        for (int m = 0; m < 2; m++)
#pragma unroll
            for (int i = 0; i < 8; i++)
#pragma unroll
                for (int j = 0; j < 4; j++) acc[m][i][j] = 0.f;
        for (int kc = 0; kc < 4; kc++) {
            const int ci = kc * 8 + q;
            uint32_t a[2][4];
#pragma unroll
            for (int mf = 0; mf < 2; mf++) {
                int la = lr0 + mf * 16, lc = la + 8;
                a[mf][0] = x_s[la * SMS + ci];
                a[mf][1] = x_s[lc * SMS + ci];
                a[mf][2] = x_s[la * SMS + ci + 4];
                a[mf][3] = x_s[lc * SMS + ci + 4];
            }
            const uint4* bp = B0 + (size_t)(kc * 16 + wn * 8) * 32 + lane;
#pragma unroll
            for (int nc = 0; nc < 8; nc++) {
                uint4 b = bp[nc * 32];
                mma16816(acc[0][nc], a[0], b.x, b.y);
                mma16816(acc[0][nc], a[0], b.z, b.w);
                mma16816(acc[1][nc], a[1], b.x, b.y);
                mma16816(acc[1][nc], a[1], b.z, b.w);
            }
        }
#pragma unroll
        for (int nc = 0; nc < 8; nc++) {
            int col = wn * 64 + nc * 8 + 2 * q;
#pragma unroll
            for (int mf = 0; mf < 2; mf++) {
                int ra = gb + lr0 + mf * 16, rc = ra + 8;
                if (ra < M) yb[(size_t)ra * 64 + (col >> 1)] =
                    packbf(acc[mf][nc][0], acc[mf][nc][1]);
                if (rc < M) yb[(size_t)rc * 64 + (col >> 1)] =
                    packbf(acc[mf][nc][2], acc[mf][nc][3]);
            }
        }
    }
}

// ================= fused agg(prev layer, ybIn) + GEMM(this layer, ybOut) =======
__global__ void __launch_bounds__(256) fused_agg_gemm(
    const uint32_t* __restrict__ ybIn,
    const float* __restrict__ bl, int outc,
    const uint4* __restrict__ Bp, int K,
    uint32_t* __restrict__ embp, uint32_t* __restrict__ ybOut, int M) {
    const int tid = threadIdx.x;
    const int wid = tid >> 5, lane = tid & 31;
    const int gb = blockIdx.x * 128;

    // ---- agg phase: 4 nodes/warp/iter, 4 iters -> 128 nodes ----
    {
        int quad = lane >> 3, h = lane & 7;
#pragma unroll 1
        for (int g = 0; g < 4; g++) {
            int n = gb + g * 32 + wid * 4 + quad;
            if (n < M) agg_node(ybIn, n, h, bl, outc);
        }
    }
    __syncthreads();  // agg writes to embp visible to block

    // ---- GEMM phase (NTILE=128) ----
    const int wm = wid >> 1, wn = wid & 1;
    const int q = lane & 3, tq = lane >> 2;
    const int rb = gb + wm * 32 + tq;
    float acc[2][8][4];
#pragma unroll
    for (int m = 0; m < 2; m++)
#pragma unroll
        for (int i = 0; i < 8; i++)
#pragma unroll
            for (int j = 0; j < 4; j++) acc[m][i][j] = 0.f;

    for (int kc = 0; kc < K / 16; kc++) {
        const int ci = kc * 8 + q;
        uint32_t a[2][4];
#pragma unroll
        for (int mf = 0; mf < 2; mf++) {
            int ra = rb + mf * 16, rc = ra + 8;
            uint32_t a0 = 0, a1 = 0, a2 = 0, a3 = 0;
            if (ra < M) {
                a0 = embp[(size_t)ra * 128 + ci];
                a2 = embp[(size_t)ra * 128 + ci + 4];
            }
            if (rc < M) {
                a1 = embp[(size_t)rc * 128 + ci];
                a3 = embp[(size_t)rc * 128 + ci + 4];
            }
            a[mf][0] = a0; a[mf][1] = a1; a[mf][2] = a2; a[mf][3] = a3;
        }
        const uint4* bp = Bp + (size_t)(kc * 16 + wn * 8) * 32 + lane;
#pragma unroll
        for (int nc = 0; nc < 8; nc++) {
            uint4 b = bp[nc * 32];
            mma16816(acc[0][nc], a[0], b.x, b.y);
            mma16816(acc[0][nc], a[0], b.z, b.w);
            mma16816(acc[1][nc], a[1], b.x, b.y);
            mma16816(acc[1][nc], a[1], b.z, b.w);
        }
    }

#pragma unroll
    for (int nc = 0; nc < 8; nc++) {
        int col = wn * 64 + nc * 8 + 2 * q;
#pragma unroll
        for (int mf = 0; mf < 2; mf++) {
            int ra = rb + mf * 16, rc = ra + 8;
            if (ra < M) ybOut[(size_t)ra * 64 + (col >> 1)] =
                packbf(acc[mf][nc][0], acc[mf][nc][1]);
            if (rc < M) ybOut[(size_t)rc * 64 + (col >> 1)] =
                packbf(acc[mf][nc][2], acc[mf][nc][3]);
        }
    }
}

// ================= fused agg(layer2, ybIn) + block column-sum ==================
__global__ void __launch_bounds__(256) fused_agg_colsum(
    const uint32_t* __restrict__ ybIn,
    const float* __restrict__ bl, const uint32_t* __restrict__ embp, int M) {
    __shared__ float sh0[256], sh1[256];
    const int tid = threadIdx.x;
    const int wid = tid >> 5, lane = tid & 31;
    const int gb = blockIdx.x * 128;

    // ---- agg phase (outc = 96) ----
    {
        int quad = lane >> 3, h = lane & 7;
#pragma unroll 1
        for (int g = 0; g < 4; g++) {
            int n = gb + g * 32 + wid * 4 + quad;
            if (n < M) agg_node(ybIn, n, h, bl, 96);
        }
    }
    __syncthreads();

    // ---- colsum phase: thread t handles col (t&127), rows half (t>>7) ----
    {
        int col = tid & 127, rh = tid >> 7;
        float s0 = 0.f, s1 = 0.f;
        for (int r = rh * 64; r < rh * 64 + 64; r++) {
            int n = gb + r;
            if (n < M) {
                uint32_t w = embp[(size_t)n * 128 + col];
                s0 += bflo(w);
                s1 += bfhi(w);
            }
        }
        sh0[tid] = s0;
        sh1[tid] = s1;
        __syncthreads();
        if (tid < 128) {
            atomicAdd(&g_s[2 * tid],     sh0[tid] + sh0[tid + 128]);
            atomicAdd(&g_s[2 * tid + 1], sh1[tid] + sh1[tid + 128]);
        }
    }
}

// ================= post mlp =================
__global__ void post_kernel(const float* __restrict__ w1, const float* __restrict__ b1,
                            const float* __restrict__ w2, const float* __restrict__ b2,
                            const float* __restrict__ w3, const float* __restrict__ b3,
                            const float* __restrict__ w4, const float* __restrict__ b4,
                            float* __restrict__ out) {
    __shared__ float s1[64], s2[64], s3[256];
    int t = threadIdx.x;
    if (t < 64) {
        float a = b1[t];
        for (int k = 0; k < 256; k++) a += g_s[k] * w1[k * 64 + t];
        s1[t] = (a > 0.f) ? a : 0.1f * a;
    }
    __syncthreads();
    if (t < 64) {
        float a = b2[t];
        for (int k = 0; k < 64; k++) a += s1[k] * w2[k * 64 + t];
        s2[t] = fmaxf(a, 0.f);
    }
    __syncthreads();
    {
        float a = b3[t];
        for (int k = 0; k < 64; k++) a += s2[k] * w3[k * 256 + t];
        s3[t] = fmaxf(a, 0.f);
    }
    __syncthreads();
    if (t < 64) {
        float a = b4[t];
        for (int k = 0; k < 256; k++) a += s3[k] * w4[k * 64 + t];
        out[t] = a;
    }
}

// ================= launch =================
extern "C" void kernel_launch(void* const* d_in, const int* in_sizes, int n_in,
                              void* d_out, int out_size) {
    const float* node_features = (const float*)d_in[0];
    const int*   edge_index    = (const int*)d_in[1];
    const float* pre_w1 = (const float*)d_in[2];
    const float* pre_b1 = (const float*)d_in[3];
    const float* pre_w2 = (const float*)d_in[4];
    const float* pre_b2 = (const float*)d_in[5];
    const float* skip   = (const float*)d_in[6];
    const float* wl[3] = {(const float*)d_in[7], (const float*)d_in[10], (const float*)d_in[13]};
    const float* bl[3] = {(const float*)d_in[8], (const float*)d_in[11], (const float*)d_in[14]};
    const float* wr[3] = {(const float*)d_in[9], (const float*)d_in[12], (const float*)d_in[15]};
    const float* post_w1 = (const float*)d_in[16];
    const float* post_b1 = (const float*)d_in[17];
    const float* post_w2 = (const float*)d_in[18];
    const float* post_b2 = (const float*)d_in[19];
    const float* post_w3 = (const float*)d_in[20];
    const float* post_b3 = (const float*)d_in[21];
    const float* post_w4 = (const float*)d_in[22];
    const float* post_b4 = (const float*)d_in[23];
    float* out = (float*)d_out;

    uint32_t *p_embp, *p_yb0, *p_yb1;
    unsigned short* p_Bp;
    cudaGetSymbolAddress((void**)&p_embp, g_embp);
    cudaGetSymbolAddress((void**)&p_yb0, g_yb0);
    cudaGetSymbolAddress((void**)&p_yb1, g_yb1);
    cudaGetSymbolAddress((void**)&p_Bp, g_Bp);

    const int NB = (NN + 255) / 256;  // 196
    const int MB = (NN + 127) / 128;  // 391

    cudaStream_t s2;
    cudaStreamCreateWithFlags(&s2, cudaStreamNonBlocking);
    cudaEvent_t eFork, eJoin;
    cudaEventCreateWithFlags(&eFork, cudaEventDisableTiming);
    cudaEventCreateWithFlags(&eJoin, cudaEventDisableTiming);

    cudaEventRecord(eFork, 0);
    cudaStreamWaitEvent(s2, eFork, 0);

    // --- side stream: CSR build (independent of pre-MLP pipeline) ---
    zero_kernel<<<NB, 256, 0, s2>>>();
    hist2_kernel<<<(EE / 2 + 255) / 256, 256, 0, s2>>>(edge_index);
    part_kernel<<<NB, 256, 0, s2>>>();
    fill2_kernel<<<NB, 256, 0, s2>>>(NB);
    scatter2_kernel<<<(EE / 2 + 255) / 256, 256, 0, s2>>>(edge_index);
    cudaEventRecord(eJoin, s2);

    // --- main stream: pack + fused pre-MLP + L0 (-> yb0) ---
    packAll_kernel<<<(61440 + 255) / 256, 256>>>(pre_w1, pre_w2, wl[0], wr[0], wl[1], wr[1],
                                                 wl[2], wr[2], skip);
    fused_pre_kernel<<<MB, 256>>>(
        node_features, (const uint4*)(p_Bp), pre_b1,
        (const uint4*)(p_Bp + 16384), pre_b2,
        (const uint4*)(p_Bp + 24576), p_embp, p_yb0, NN);

    // join: agg needs the CSR
    cudaStreamWaitEvent(0, eJoin, 0);

    // [agg0(yb0) + gemm L1 -> yb1], [agg1(yb1) + gemm L2 -> yb0], [agg2(yb0) + colsum]
    fused_agg_gemm<<<MB, 256>>>(p_yb0, bl[0], 32, (const uint4*)(p_Bp + 40960), 128,
                                p_embp, p_yb1, NN);
    fused_agg_gemm<<<MB, 256>>>(p_yb1, bl[1], 64, (const uint4*)(p_Bp + 73728), 192,
                                p_embp, p_yb0, NN);
    fused_agg_colsum<<<MB, 256>>>(p_yb0, bl[2], p_embp, NN);

    post_kernel<<<1, 256>>>(post_w1, post_b1, post_w2, post_b2, post_w3, post_b3,
                            post_w4, post_b4, out);

    cudaEventDestroy(eFork);
    cudaEventDestroy(eJoin);
    cudaStreamDestroy(s2);
}